// round 2
// baseline (speedup 1.0000x reference)
#include <cuda_runtime.h>
#include <math.h>

#define TN  256
#define BN  512
#define INN 128
#define MN  256
#define GN  768   // 3 gates * M
#define K2  512   // 2 children * M

// -------- device scratch (no allocations allowed) --------
__device__ float g_G[(size_t)TN * BN * GN];   // gate pre-activations, ~402MB
__device__ float g_W1[INN * GN];              // input weights, k-major
__device__ float g_W2[K2 * GN];               // recurrent weights, k-major
__device__ float g_bvec[GN];
__device__ int   g_child0[TN * BN];
__device__ int   g_child1[TN * BN];
__device__ int   g_root[BN];

__device__ __forceinline__ float sigf(float x) { return 1.0f / (1.0f + expf(-x)); }

// -------- prep: reorder weights to k-major [k][gate*M+m] --------
__global__ void prep_kernel(const float* __restrict__ Wi, const float* __restrict__ bi,
                            const float* __restrict__ Wo, const float* __restrict__ bo,
                            const float* __restrict__ Wu, const float* __restrict__ bu,
                            const float* __restrict__ Ui, const float* __restrict__ Uo,
                            const float* __restrict__ Uu) {
    int idx = blockIdx.x * blockDim.x + threadIdx.x;
    int stride = gridDim.x * blockDim.x;
    for (int i = idx; i < INN * GN; i += stride) {
        int k = i / GN, n = i % GN;
        int g = n / MN, m = n % MN;
        const float* W = (g == 0) ? Wi : ((g == 1) ? Wo : Wu);
        g_W1[i] = W[m * INN + k];
    }
    for (int i = idx; i < K2 * GN; i += stride) {
        int k = i / GN, n = i % GN;
        int g = n / MN, m = n % MN;
        const float* U = (g == 0) ? Ui : ((g == 1) ? Uo : Uu);
        int br = k / MN, kk = k % MN;
        g_W2[i] = U[br * MN * MN + m * MN + kk];
    }
    for (int i = idx; i < GN; i += stride) {
        int g = i / MN, m = i % MN;
        const float* bb = (g == 0) ? bi : ((g == 1) ? bo : bu);
        g_bvec[i] = bb[m];
    }
}

// -------- stack simulation: one thread per tree --------
__global__ void stacksim_kernel(const int* __restrict__ arities) {
    int b = threadIdx.x;  // blockDim = BN, 1 block
    int stck[TN + 2];
    #pragma unroll 8
    for (int i = 0; i < TN + 2; i++) stck[i] = 0;
    int sp = 1;  // BF - 1
    for (int t = 0; t < TN; t++) {
        int a = arities[t * BN + b];
        int c0 = -1, c1 = -1;
        if (a > 0) {
            int s = stck[max(sp, 0)];
            if (s < t) c0 = s;                 // s>=t => memory slot unwritten => zeros
        }
        if (a > 1) {
            int s = stck[max(sp - 1, 0)];
            if (s < t) c1 = s;
        }
        g_child0[t * BN + b] = c0;
        g_child1[t * BN + b] = c1;
        sp += 1 - abs(a);
        if (sp < 0) sp = 0;
        if (sp > TN + 1) sp = TN + 1;
        if (a != -1) stck[sp] = t;
    }
    g_root[b] = stck[max(sp, 0)];
}

// -------- input GEMM: G[t*B+b][n] = X[row]@W1 + bvec --------
// grid: (TB/64, GN/64), 256 threads. Tiles 64x64, K tiled by 64.
__global__ __launch_bounds__(256) void gemm_in_kernel(const float* __restrict__ X) {
    __shared__ float As[64 * 68];   // 64 rows x 64 k, pad 68 (16B-aligned, conflict-free)
    __shared__ float Ws[64 * 64];   // 64 k x 64 n
    int tid = threadIdx.x;
    int rtile = blockIdx.x * 64;
    int ntile = blockIdx.y * 64;
    int r0 = (tid >> 4) << 2;   // (tid/16)*4
    int n0 = (tid & 15) << 2;   // (tid%16)*4
    float acc[4][4] = {};

    for (int kb = 0; kb < INN; kb += 64) {
        #pragma unroll
        for (int j = 0; j < 4; j++) {
            int id = tid + j * 256;
            int row = id >> 4, k4 = (id & 15) << 2;
            float4 v = *(const float4*)(X + (rtile + row) * INN + kb + k4);
            *(float4*)(As + row * 68 + k4) = v;
            float4 w = *(const float4*)(g_W1 + (kb + row) * GN + ntile + k4);
            *(float4*)(Ws + row * 64 + k4) = w;
        }
        __syncthreads();
        #pragma unroll 16
        for (int kk = 0; kk < 64; kk++) {
            float4 wv = *(float4*)(Ws + kk * 64 + n0);
            float w[4] = {wv.x, wv.y, wv.z, wv.w};
            #pragma unroll
            for (int i = 0; i < 4; i++) {
                float a = As[(r0 + i) * 68 + kk];
                #pragma unroll
                for (int j = 0; j < 4; j++) acc[i][j] += a * w[j];
            }
        }
        __syncthreads();
    }

    float4 bv = *(const float4*)(g_bvec + ntile + n0);
    float bb[4] = {bv.x, bv.y, bv.z, bv.w};
    #pragma unroll
    for (int i = 0; i < 4; i++) {
        float4 o;
        o.x = acc[i][0] + bb[0];
        o.y = acc[i][1] + bb[1];
        o.z = acc[i][2] + bb[2];
        o.w = acc[i][3] + bb[3];
        *(float4*)(g_G + (size_t)(rtile + r0 + i) * GN + ntile + n0) = o;
    }
}

// -------- per-step kernel: recurrent GEMM (if children active) + gate fusion --------
// grid: (B/64, M/32) = (8,8), 256 threads. Thread: 2 b-rows x 4 m x 3 gates.
__global__ __launch_bounds__(256) void step_kernel(int t, float* __restrict__ hmem) {
    __shared__ int   c0s[64], c1s[64];
    __shared__ float As[64 * 68];        // 64 b x 64 k tile (gathered children)
    __shared__ float Ws[3 * 64 * 32];    // 3 gates x 64 k x 32 m
    int tid = threadIdx.x;
    int btile = blockIdx.x * 64;
    int mtile = blockIdx.y * 32;

    if (tid < 64) {
        c0s[tid] = g_child0[t * BN + btile + tid];
        c1s[tid] = g_child1[t * BN + btile + tid];
    }
    __syncthreads();
    int act = __syncthreads_or((tid < 64) ? ((c0s[tid] >= 0) | (c1s[tid] >= 0)) : 0);

    int brow = tid >> 3;          // 0..31
    int m0   = (tid & 7) << 2;    // 0..28
    float acc[2][3][4] = {};

    if (act) {
        for (int kb = 0; kb < K2; kb += 64) {
            // gather A tile: child h rows (zeros for masked children)
            #pragma unroll
            for (int j = 0; j < 4; j++) {
                int id = tid + j * 256;
                int row = id >> 4, k4 = (id & 15) << 2;
                int k = kb + k4;
                int c = (k < MN) ? c0s[row] : c1s[row];
                float4 v = make_float4(0.f, 0.f, 0.f, 0.f);
                if (c >= 0)
                    v = *(const float4*)(hmem + (c * BN + btile + row) * MN + (k & (MN - 1)));
                *(float4*)(As + row * 68 + k4) = v;
            }
            // load W2 tile: 3 gates x 64 k x 32 m
            #pragma unroll
            for (int j = 0; j < 6; j++) {
                int id = tid + j * 256;
                int g = id >> 9;
                int rem = id & 511;
                int kk = rem >> 3;
                int m4 = (rem & 7) << 2;
                float4 w = *(const float4*)(g_W2 + (kb + kk) * GN + g * MN + mtile + m4);
                *(float4*)(Ws + g * 2048 + kk * 32 + m4) = w;
            }
            __syncthreads();
            #pragma unroll 8
            for (int kk = 0; kk < 64; kk++) {
                float a0 = As[brow * 68 + kk];
                float a1 = As[(brow + 32) * 68 + kk];
                #pragma unroll
                for (int g = 0; g < 3; g++) {
                    float4 wv = *(float4*)(Ws + g * 2048 + kk * 32 + m0);
                    float w[4] = {wv.x, wv.y, wv.z, wv.w};
                    #pragma unroll
                    for (int j = 0; j < 4; j++) {
                        acc[0][g][j] += a0 * w[j];
                        acc[1][g][j] += a1 * w[j];
                    }
                }
            }
            __syncthreads();
        }
    }

    // epilogue: add precomputed input gates, apply LSTM nonlinearity, write h
    #pragma unroll
    for (int r = 0; r < 2; r++) {
        int b = btile + brow + r * 32;
        const float* Gp = g_G + ((size_t)t * BN + b) * GN;
        float4 gi4 = *(const float4*)(Gp + 0 * MN + mtile + m0);
        float4 go4 = *(const float4*)(Gp + 1 * MN + mtile + m0);
        float4 gu4 = *(const float4*)(Gp + 2 * MN + mtile + m0);
        float gi[4] = {gi4.x, gi4.y, gi4.z, gi4.w};
        float go[4] = {go4.x, go4.y, go4.z, go4.w};
        float gu[4] = {gu4.x, gu4.y, gu4.z, gu4.w};
        float h[4];
        #pragma unroll
        for (int j = 0; j < 4; j++) {
            float vi = gi[j] + acc[r][0][j];
            float vo = go[j] + acc[r][1][j];
            float vu = gu[j] + acc[r][2][j];
            float cc = sigf(vi) * tanhf(vu);
            h[j] = sigf(vo) * tanhf(cc);
        }
        float4 hv = make_float4(h[0], h[1], h[2], h[3]);
        *(float4*)(hmem + (t * BN + b) * MN + mtile + m0) = hv;
    }
}

// -------- root gather --------
__global__ void root_kernel(float* __restrict__ out, const float* __restrict__ hmem) {
    int b = blockIdx.x;
    int m = threadIdx.x;
    out[b * MN + m] = hmem[(g_root[b] * BN + b) * MN + m];
}

extern "C" void kernel_launch(void* const* d_in, const int* in_sizes, int n_in,
                              void* d_out, int out_size) {
    const float* X   = (const float*)d_in[0];
    const int*   ar  = (const int*)  d_in[1];
    const float* Wi  = (const float*)d_in[2];
    const float* bi  = (const float*)d_in[3];
    const float* Wo  = (const float*)d_in[4];
    const float* bo  = (const float*)d_in[5];
    const float* Wu  = (const float*)d_in[6];
    const float* bu  = (const float*)d_in[7];
    // d_in[8] = Wf, d_in[9] = bf_b : dead code in reference
    const float* Ui  = (const float*)d_in[10];
    const float* Uo  = (const float*)d_in[11];
    const float* Uu  = (const float*)d_in[12];
    // d_in[13] = Uf : dead code

    float* out  = (float*)d_out;
    float* hmem = out + BN * MN;   // [T,B,M] h-memory region of the output

    prep_kernel<<<128, 256>>>(Wi, bi, Wo, bo, Wu, bu, Ui, Uo, Uu);
    stacksim_kernel<<<1, BN>>>(ar);
    gemm_in_kernel<<<dim3((TN * BN) / 64, GN / 64), 256>>>(X);
    for (int t = 0; t < TN; t++)
        step_kernel<<<dim3(BN / 64, MN / 32), 256>>>(t, hmem);
    root_kernel<<<BN, MN>>>(out, hmem);
}

// round 3
// speedup vs baseline: 2.8284x; 2.8284x over previous
#include <cuda_runtime.h>
#include <math.h>

#define TN  256
#define BN  512
#define INN 128
#define MN  256
#define GN  768   // 3 gates * M
#define K2  512   // 2 children * M
#define GRID_P 296

// -------- device scratch --------
__device__ float g_G[(size_t)TN * BN * GN];   // gate pre-activations
__device__ float g_W1[INN * GN];              // input weights, k-major
__device__ float g_W2[K2 * GN];               // recurrent weights, k-major
__device__ float g_bvec[GN];
__device__ int   g_child0[TN * BN];
__device__ int   g_child1[TN * BN];
__device__ int   g_root[BN];
__device__ int   g_order[TN];
__device__ int   g_lvlstart[TN + 2];
__device__ int   g_numlevels;
__device__ unsigned g_barcnt;

__device__ __forceinline__ float sigf(float x) { return 1.0f / (1.0f + expf(-x)); }

// -------- prep: reorder weights to k-major [k][gate*M+m] --------
__global__ void prep_kernel(const float* __restrict__ Wi, const float* __restrict__ bi,
                            const float* __restrict__ Wo, const float* __restrict__ bo,
                            const float* __restrict__ Wu, const float* __restrict__ bu,
                            const float* __restrict__ Ui, const float* __restrict__ Uo,
                            const float* __restrict__ Uu) {
    int idx = blockIdx.x * blockDim.x + threadIdx.x;
    int stride = gridDim.x * blockDim.x;
    for (int i = idx; i < INN * GN; i += stride) {
        int k = i / GN, n = i % GN;
        int g = n / MN, m = n % MN;
        const float* W = (g == 0) ? Wi : ((g == 1) ? Wo : Wu);
        g_W1[i] = W[m * INN + k];
    }
    for (int i = idx; i < K2 * GN; i += stride) {
        int k = i / GN, n = i % GN;
        int g = n / MN, m = n % MN;
        const float* U = (g == 0) ? Ui : ((g == 1) ? Uo : Uu);
        int br = k / MN, kk = k % MN;
        g_W2[i] = U[br * MN * MN + m * MN + kk];
    }
    for (int i = idx; i < GN; i += stride) {
        int g = i / MN, m = i % MN;
        const float* bb = (g == 0) ? bi : ((g == 1) ? bo : bu);
        g_bvec[i] = bb[m];
    }
}

// -------- scheduler: stack sim + dependency levels + wavefront order --------
__global__ void sched_kernel(const int* __restrict__ arities) {
    __shared__ int s_lvl[TN];
    __shared__ int s_start[TN + 1];
    __shared__ int s_cur[TN + 1];
    __shared__ int s_max;
    int b = threadIdx.x;  // 512 threads
    for (int i = b; i < TN; i += BN) s_lvl[i] = 0;
    for (int i = b; i < TN + 1; i += BN) s_cur[i] = 0;
    if (b == 0) { s_max = 0; g_barcnt = 0u; }
    __syncthreads();

    int stck[TN + 2];
    int lvl[TN];
    #pragma unroll 8
    for (int i = 0; i < TN + 2; i++) stck[i] = 0;
    int sp = 1;  // BF - 1
    for (int t = 0; t < TN; t++) {
        int a = arities[t * BN + b];
        int c0 = -1, c1 = -1;
        if (a > 0) { int s = stck[max(sp, 0)];     if (s < t) c0 = s; }
        if (a > 1) { int s = stck[max(sp - 1, 0)]; if (s < t) c1 = s; }
        g_child0[t * BN + b] = c0;
        g_child1[t * BN + b] = c1;
        int L = 0;
        if (c0 >= 0) L = lvl[c0] + 1;
        if (c1 >= 0) L = max(L, lvl[c1] + 1);
        lvl[t] = L;
        atomicMax(&s_lvl[t], L);
        sp += 1 - abs(a);
        if (sp < 0) sp = 0;
        if (sp > TN + 1) sp = TN + 1;
        if (a != -1) stck[sp] = t;
    }
    g_root[b] = stck[max(sp, 0)];
    __syncthreads();

    if (b < TN) { atomicMax(&s_max, s_lvl[b]); atomicAdd(&s_cur[s_lvl[b]], 1); }
    __syncthreads();
    if (b == 0) {
        int nl = s_max + 1;
        int pos = 0;
        for (int L = 0; L < nl; L++) {
            s_start[L] = pos;
            g_lvlstart[L] = pos;
            pos += s_cur[L];
            s_cur[L] = 0;
        }
        g_lvlstart[nl] = pos;
        g_numlevels = nl;
    }
    __syncthreads();
    if (b < TN) {
        int L = s_lvl[b];
        int p = atomicAdd(&s_cur[L], 1);
        g_order[s_start[L] + p] = b;
    }
}

// -------- input GEMM: G = X @ W1 + b, tiles 128x64, k-tile 32, 8x4/thread --------
__global__ __launch_bounds__(256) void gemm_in_kernel(const float* __restrict__ X) {
    __shared__ float As[128 * 36];
    __shared__ float Ws[32 * 64];
    int tid = threadIdx.x;
    int rtile = blockIdx.x * 128;
    int ntile = blockIdx.y * 64;
    int r0 = (tid >> 4) << 2;
    int n0 = (tid & 15) << 2;
    float acc[8][4] = {};

    for (int kb = 0; kb < INN; kb += 32) {
        #pragma unroll
        for (int j = 0; j < 4; j++) {
            int id = tid + j * 256;
            int row = id >> 3, k4 = (id & 7) << 2;
            float4 v = *(const float4*)(X + (size_t)(rtile + row) * INN + kb + k4);
            *(float4*)(As + row * 36 + k4) = v;
        }
        #pragma unroll
        for (int j = 0; j < 2; j++) {
            int id = tid + j * 256;
            int kk = id >> 4, n4 = (id & 15) << 2;
            *(float4*)(Ws + kk * 64 + n4) = *(const float4*)(g_W1 + (size_t)(kb + kk) * GN + ntile + n4);
        }
        __syncthreads();
        #pragma unroll
        for (int kk = 0; kk < 32; kk++) {
            float4 wv = *(float4*)(Ws + kk * 64 + n0);
            float a[8];
            #pragma unroll
            for (int i = 0; i < 4; i++) {
                a[i]     = As[(r0 + i) * 36 + kk];
                a[i + 4] = As[(r0 + i + 64) * 36 + kk];
            }
            #pragma unroll
            for (int i = 0; i < 8; i++) {
                acc[i][0] += a[i] * wv.x;
                acc[i][1] += a[i] * wv.y;
                acc[i][2] += a[i] * wv.z;
                acc[i][3] += a[i] * wv.w;
            }
        }
        __syncthreads();
    }

    float4 bv = *(const float4*)(g_bvec + ntile + n0);
    #pragma unroll
    for (int i = 0; i < 8; i++) {
        int row = rtile + r0 + ((i < 4) ? i : (60 + i));
        float4 o;
        o.x = acc[i][0] + bv.x;
        o.y = acc[i][1] + bv.y;
        o.z = acc[i][2] + bv.z;
        o.w = acc[i][3] + bv.w;
        *(float4*)(g_G + (size_t)row * GN + ntile + n0) = o;
    }
}

// -------- grid barrier --------
__device__ __forceinline__ void grid_sync(unsigned& target) {
    __syncthreads();
    if (threadIdx.x == 0) {
        __threadfence();
        atomicAdd(&g_barcnt, 1u);
        volatile unsigned* p = &g_barcnt;
        while (*p < target) { __nanosleep(32); }
        __threadfence();
    }
    __syncthreads();
    target += gridDim.x;
}

// -------- persistent wavefront kernel --------
// Phase A per level: recurrent GEMM tiles (128 b-rows x 64 gate-cols, K=512) -> G += childH @ W2
// Phase B per level: fused LSTM nonlinearity -> hmem
__global__ __launch_bounds__(256, 2) void persist_kernel(float* __restrict__ hmem) {
    __shared__ int   c0s[128], c1s[128];
    __shared__ float As[128 * 36];
    __shared__ float Ws[32 * 64];
    int tid = threadIdx.x;
    unsigned target = gridDim.x;
    int nlev = g_numlevels;

    for (int L = 0; L < nlev; L++) {
        int s0 = g_lvlstart[L];
        int nsteps = g_lvlstart[L + 1] - s0;

        // ---- phase A: GEMM ----
        int ntasks = nsteps * 48;  // (512/128)*(768/64) tiles per step
        for (int task = blockIdx.x; task < ntasks; task += gridDim.x) {
            int t = g_order[s0 + task / 48];
            int tile = task % 48;
            int btile = (tile & 3) * 128;
            int ntile = (tile >> 2) * 64;

            if (tid < 128) {
                c0s[tid] = g_child0[t * BN + btile + tid];
                c1s[tid] = g_child1[t * BN + btile + tid];
            }
            __syncthreads();
            int act = __syncthreads_or((tid < 128) ? ((c0s[tid] >= 0) | (c1s[tid] >= 0)) : 0);
            if (!act) continue;

            int r0 = (tid >> 4) << 2;
            int n0 = (tid & 15) << 2;
            float acc[8][4] = {};

            for (int kb = 0; kb < K2; kb += 32) {
                int lower = (kb < MN);
                int colb = kb & (MN - 1);
                #pragma unroll
                for (int j = 0; j < 4; j++) {
                    int id = tid + j * 256;
                    int row = id >> 3, k4 = (id & 7) << 2;
                    int c = lower ? c0s[row] : c1s[row];
                    float4 v = make_float4(0.f, 0.f, 0.f, 0.f);
                    if (c >= 0)
                        v = *(const float4*)(hmem + ((size_t)c * BN + btile + row) * MN + colb + k4);
                    *(float4*)(As + row * 36 + k4) = v;
                }
                #pragma unroll
                for (int j = 0; j < 2; j++) {
                    int id = tid + j * 256;
                    int kk = id >> 4, n4 = (id & 15) << 2;
                    *(float4*)(Ws + kk * 64 + n4) =
                        *(const float4*)(g_W2 + (size_t)(kb + kk) * GN + ntile + n4);
                }
                __syncthreads();
                #pragma unroll
                for (int kk = 0; kk < 32; kk++) {
                    float4 wv = *(float4*)(Ws + kk * 64 + n0);
                    float a[8];
                    #pragma unroll
                    for (int i = 0; i < 4; i++) {
                        a[i]     = As[(r0 + i) * 36 + kk];
                        a[i + 4] = As[(r0 + i + 64) * 36 + kk];
                    }
                    #pragma unroll
                    for (int i = 0; i < 8; i++) {
                        acc[i][0] += a[i] * wv.x;
                        acc[i][1] += a[i] * wv.y;
                        acc[i][2] += a[i] * wv.z;
                        acc[i][3] += a[i] * wv.w;
                    }
                }
                __syncthreads();
            }
            #pragma unroll
            for (int i = 0; i < 8; i++) {
                int row = btile + r0 + ((i < 4) ? i : (60 + i));
                float* p = g_G + ((size_t)t * BN + row) * GN + ntile + n0;
                float4 g = *(float4*)p;
                g.x += acc[i][0];
                g.y += acc[i][1];
                g.z += acc[i][2];
                g.w += acc[i][3];
                *(float4*)p = g;
            }
        }
        grid_sync(target);

        // ---- phase B: epilogue ----
        int etasks = nsteps * 128;  // 512*256/(256 thr * 4 elem)
        for (int task = blockIdx.x; task < etasks; task += gridDim.x) {
            int t = g_order[s0 + (task >> 7)];
            int sub = task & 127;
            int q = sub * 256 + tid;
            int b = q >> 6;
            int m0 = (q & 63) << 2;
            const float* Gp = g_G + ((size_t)t * BN + b) * GN;
            float4 gi = *(const float4*)(Gp + m0);
            float4 go = *(const float4*)(Gp + MN + m0);
            float4 gu = *(const float4*)(Gp + 2 * MN + m0);
            float vi[4] = {gi.x, gi.y, gi.z, gi.w};
            float vo[4] = {go.x, go.y, go.z, go.w};
            float vu[4] = {gu.x, gu.y, gu.z, gu.w};
            float h[4];
            #pragma unroll
            for (int j = 0; j < 4; j++) {
                float cc = sigf(vi[j]) * tanhf(vu[j]);
                h[j] = sigf(vo[j]) * tanhf(cc);
            }
            *(float4*)(hmem + ((size_t)t * BN + b) * MN + m0) =
                make_float4(h[0], h[1], h[2], h[3]);
        }
        grid_sync(target);
    }
}

// -------- root gather --------
__global__ void root_kernel(float* __restrict__ out, const float* __restrict__ hmem) {
    int b = blockIdx.x;
    int m = threadIdx.x;
    out[b * MN + m] = hmem[((size_t)g_root[b] * BN + b) * MN + m];
}

extern "C" void kernel_launch(void* const* d_in, const int* in_sizes, int n_in,
                              void* d_out, int out_size) {
    const float* X  = (const float*)d_in[0];
    const int*   ar = (const int*)  d_in[1];
    const float* Wi = (const float*)d_in[2];
    const float* bi = (const float*)d_in[3];
    const float* Wo = (const float*)d_in[4];
    const float* bo = (const float*)d_in[5];
    const float* Wu = (const float*)d_in[6];
    const float* bu = (const float*)d_in[7];
    // d_in[8]=Wf, d_in[9]=bf_b dead code
    const float* Ui = (const float*)d_in[10];
    const float* Uo = (const float*)d_in[11];
    const float* Uu = (const float*)d_in[12];
    // d_in[13]=Uf dead code

    float* out  = (float*)d_out;
    float* hmem = out + BN * MN;  // [T,B,M] region of output

    prep_kernel<<<128, 256>>>(Wi, bi, Wo, bo, Wu, bu, Ui, Uo, Uu);
    sched_kernel<<<1, BN>>>(ar);
    gemm_in_kernel<<<dim3((TN * BN) / 128, GN / 64), 256>>>(X);
    persist_kernel<<<GRID_P, 256>>>(hmem);
    root_kernel<<<BN, MN>>>(out, hmem);
}

// round 7
// speedup vs baseline: 4.2354x; 1.4974x over previous
#include <cuda_runtime.h>
#include <cuda_bf16.h>
#include <math.h>
#include <stdint.h>

#define TN  256
#define BN  512
#define INN 128
#define MN  256
#define GN  768
#define K2  512
#define GRID_P 296
#define SP  40   // padded smem row stride in bf16 (32 k + 8 pad)

// -------- device scratch --------
__device__ float g_G[(size_t)TN * BN * GN];
__device__ __nv_bfloat16 g_W1hi[GN * INN];
__device__ __nv_bfloat16 g_W1lo[GN * INN];
__device__ __nv_bfloat16 g_W2hi[GN * K2];
__device__ __nv_bfloat16 g_W2lo[GN * K2];
__device__ float g_bvec[GN];
__device__ int   g_child0[TN * BN];
__device__ int   g_child1[TN * BN];
__device__ int   g_root[BN];
__device__ int   g_order[TN];
__device__ int   g_lvlstart[TN + 2];
__device__ int   g_numlevels;
__device__ unsigned g_barcnt;

__device__ __forceinline__ float sigf(float x) { return 1.0f / (1.0f + expf(-x)); }

__device__ __forceinline__ void mma16816(float* d, const uint32_t* a, const uint32_t* b) {
    asm volatile(
        "mma.sync.aligned.m16n8k16.row.col.f32.bf16.bf16.f32 "
        "{%0,%1,%2,%3}, {%4,%5,%6,%7}, {%8,%9}, {%0,%1,%2,%3};"
        : "+f"(d[0]), "+f"(d[1]), "+f"(d[2]), "+f"(d[3])
        : "r"(a[0]), "r"(a[1]), "r"(a[2]), "r"(a[3]), "r"(b[0]), "r"(b[1]));
}

__device__ __forceinline__ uint32_t packbf2(float x, float y) {
    __nv_bfloat162 v = __floats2bfloat162_rn(x, y);
    return *reinterpret_cast<uint32_t*>(&v);
}

// split 8 fp32 into hi/lo bf16 packed uint4 each
__device__ __forceinline__ void split8(float4 a, float4 b, uint4* hi, uint4* lo) {
    float f[8];
    f[0] = a.x; f[1] = a.y; f[2] = a.z; f[3] = a.w;
    f[4] = b.x; f[5] = b.y; f[6] = b.z; f[7] = b.w;
    float fh[8];
    float fl[8];
    #pragma unroll
    for (int i = 0; i < 8; i++) {
        __nv_bfloat16 h = __float2bfloat16_rn(f[i]);
        fh[i] = __bfloat162float(h);
        fl[i] = f[i] - fh[i];
    }
    hi->x = packbf2(fh[0], fh[1]); hi->y = packbf2(fh[2], fh[3]);
    hi->z = packbf2(fh[4], fh[5]); hi->w = packbf2(fh[6], fh[7]);
    lo->x = packbf2(fl[0], fl[1]); lo->y = packbf2(fl[2], fl[3]);
    lo->z = packbf2(fl[4], fl[5]); lo->w = packbf2(fl[6], fl[7]);
}

// -------- prep: split weights into bf16 hi/lo, [n][k] layout --------
__global__ void prep_kernel(const float* __restrict__ Wi, const float* __restrict__ bi,
                            const float* __restrict__ Wo, const float* __restrict__ bo,
                            const float* __restrict__ Wu, const float* __restrict__ bu,
                            const float* __restrict__ Ui, const float* __restrict__ Uo,
                            const float* __restrict__ Uu) {
    int idx = blockIdx.x * blockDim.x + threadIdx.x;
    int stride = gridDim.x * blockDim.x;
    for (int i = idx; i < GN * INN; i += stride) {
        int n = i / INN;
        int k = i % INN;
        int g = n / MN;
        int m = n % MN;
        const float* W = (g == 0) ? Wi : ((g == 1) ? Wo : Wu);
        float x = W[m * INN + k];
        __nv_bfloat16 h = __float2bfloat16_rn(x);
        g_W1hi[i] = h;
        g_W1lo[i] = __float2bfloat16_rn(x - __bfloat162float(h));
    }
    for (int i = idx; i < GN * K2; i += stride) {
        int n = i / K2;
        int k = i % K2;
        int g = n / MN;
        int m = n % MN;
        const float* U = (g == 0) ? Ui : ((g == 1) ? Uo : Uu);
        int br = k / MN;
        int kk = k % MN;
        float x = U[br * MN * MN + m * MN + kk];
        __nv_bfloat16 h = __float2bfloat16_rn(x);
        g_W2hi[i] = h;
        g_W2lo[i] = __float2bfloat16_rn(x - __bfloat162float(h));
    }
    for (int i = idx; i < GN; i += stride) {
        int g = i / MN;
        int m = i % MN;
        const float* bb = (g == 0) ? bi : ((g == 1) ? bo : bu);
        g_bvec[i] = bb[m];
    }
}

// -------- scheduler --------
__global__ void sched_kernel(const int* __restrict__ arities) {
    __shared__ int s_lvl[TN];
    __shared__ int s_start[TN + 1];
    __shared__ int s_cur[TN + 1];
    __shared__ int s_max;
    int b = threadIdx.x;
    for (int i = b; i < TN; i += BN) s_lvl[i] = 0;
    for (int i = b; i < TN + 1; i += BN) s_cur[i] = 0;
    if (b == 0) { s_max = 0; g_barcnt = 0u; }
    __syncthreads();

    int stck[TN + 2];
    int lvl[TN];
    for (int i = 0; i < TN + 2; i++) stck[i] = 0;
    int sp = 1;
    for (int t = 0; t < TN; t++) {
        int a = arities[t * BN + b];
        int c0 = -1;
        int c1 = -1;
        if (a > 0) {
            int s = stck[max(sp, 0)];
            if (s < t) c0 = s;
        }
        if (a > 1) {
            int s = stck[max(sp - 1, 0)];
            if (s < t) c1 = s;
        }
        g_child0[t * BN + b] = c0;
        g_child1[t * BN + b] = c1;
        int L = 0;
        if (c0 >= 0) L = lvl[c0] + 1;
        if (c1 >= 0) L = max(L, lvl[c1] + 1);
        lvl[t] = L;
        atomicMax(&s_lvl[t], L);
        sp += 1 - abs(a);
        if (sp < 0) sp = 0;
        if (sp > TN + 1) sp = TN + 1;
        if (a != -1) stck[sp] = t;
    }
    g_root[b] = stck[max(sp, 0)];
    __syncthreads();

    if (b < TN) {
        atomicMax(&s_max, s_lvl[b]);
        atomicAdd(&s_cur[s_lvl[b]], 1);
    }
    __syncthreads();
    if (b == 0) {
        int nl = s_max + 1;
        int pos = 0;
        for (int L = 0; L < nl; L++) {
            s_start[L] = pos;
            g_lvlstart[L] = pos;
            pos += s_cur[L];
            s_cur[L] = 0;
        }
        g_lvlstart[nl] = pos;
        g_numlevels = nl;
    }
    __syncthreads();
    if (b < TN) {
        int L = s_lvl[b];
        int p = atomicAdd(&s_cur[L], 1);
        g_order[s_start[L] + p] = b;
    }
}

// frag loaders: smem [row][k] with stride SP bf16
__device__ __forceinline__ void load_afrag(uint32_t* a, const __nv_bfloat16* base,
                                           int row, int k0, int g, int tig) {
    const __nv_bfloat16* p = base + (row + g) * SP + k0 + 2 * tig;
    a[0] = *(const uint32_t*)p;
    a[1] = *(const uint32_t*)(p + 8 * SP);
    a[2] = *(const uint32_t*)(p + 8);
    a[3] = *(const uint32_t*)(p + 8 * SP + 8);
}
__device__ __forceinline__ void load_bfrag(uint32_t* b, const __nv_bfloat16* base,
                                           int n0, int k0, int g, int tig) {
    const __nv_bfloat16* p = base + (n0 + g) * SP + k0 + 2 * tig;
    b[0] = *(const uint32_t*)p;
    b[1] = *(const uint32_t*)(p + 8);
}

// -------- input GEMM (HMMA bf16 3-term): G = X @ W1^T + bias --------
// grid ((T*B)/128, GN/64), 256 threads, block tile 128x64, k-chunk 32
__global__ __launch_bounds__(256, 2) void gemm_in_kernel(const float* __restrict__ X) {
    __shared__ __nv_bfloat16 Ahi[128 * SP];
    __shared__ __nv_bfloat16 Alo[128 * SP];
    __shared__ __nv_bfloat16 Bhi[64 * SP];
    __shared__ __nv_bfloat16 Blo[64 * SP];
    int tid = threadIdx.x;
    int lane = tid & 31;
    int w = tid >> 5;
    int wm = w >> 1;       // 0..3
    int wn = w & 1;        // 0..1
    int g = lane >> 2;
    int tig = lane & 3;
    int rtile = blockIdx.x * 128;
    int ntile = blockIdx.y * 64;

    float d[2][4][4];
    #pragma unroll
    for (int i = 0; i < 2; i++)
        #pragma unroll
        for (int j = 0; j < 4; j++)
            #pragma unroll
            for (int q = 0; q < 4; q++) d[i][j][q] = 0.f;

    for (int kb = 0; kb < INN; kb += 32) {
        #pragma unroll
        for (int j = 0; j < 2; j++) {
            int id = tid + j * 256;
            int row = id >> 2;
            int g8 = id & 3;
            const float* src = X + (size_t)(rtile + row) * INN + kb + g8 * 8;
            float4 va = *(const float4*)src;
            float4 vb = *(const float4*)(src + 4);
            uint4 hi;
            uint4 lo;
            split8(va, vb, &hi, &lo);
            *(uint4*)(Ahi + row * SP + g8 * 8) = hi;
            *(uint4*)(Alo + row * SP + g8 * 8) = lo;
        }
        {
            int id = tid;
            int n = id >> 2;
            int g8 = id & 3;
            size_t idx = (size_t)(ntile + n) * INN + kb + g8 * 8;
            *(uint4*)(Bhi + n * SP + g8 * 8) = *(const uint4*)(g_W1hi + idx);
            *(uint4*)(Blo + n * SP + g8 * 8) = *(const uint4*)(g_W1lo + idx);
        }
        __syncthreads();
        #pragma unroll
        for (int s = 0; s < 2; s++) {
            int k0 = s * 16;
            uint32_t ah[2][4];
            uint32_t al[2][4];
            uint32_t bh[4][2];
            uint32_t bl[4][2];
            #pragma unroll
            for (int mt = 0; mt < 2; mt++) {
                load_afrag(ah[mt], Ahi, wm * 32 + mt * 16, k0, g, tig);
                load_afrag(al[mt], Alo, wm * 32 + mt * 16, k0, g, tig);
            }
            #pragma unroll
            for (int nt = 0; nt < 4; nt++) {
                load_bfrag(bh[nt], Bhi, wn * 32 + nt * 8, k0, g, tig);
                load_bfrag(bl[nt], Blo, wn * 32 + nt * 8, k0, g, tig);
            }
            #pragma unroll
            for (int mt = 0; mt < 2; mt++) {
                #pragma unroll
                for (int nt = 0; nt < 4; nt++) {
                    mma16816(d[mt][nt], ah[mt], bh[nt]);
                    mma16816(d[mt][nt], ah[mt], bl[nt]);
                    mma16816(d[mt][nt], al[mt], bh[nt]);
                }
            }
        }
        __syncthreads();
    }

    // epilogue: add bias, write G
    #pragma unroll
    for (int mt = 0; mt < 2; mt++) {
        #pragma unroll
        for (int nt = 0; nt < 4; nt++) {
            int r = rtile + wm * 32 + mt * 16 + g;
            int c = ntile + wn * 32 + nt * 8 + 2 * tig;
            float2 bv = *(const float2*)(g_bvec + c);
            float2 o0;
            o0.x = d[mt][nt][0] + bv.x;
            o0.y = d[mt][nt][1] + bv.y;
            *(float2*)(g_G + (size_t)r * GN + c) = o0;
            float2 o1;
            o1.x = d[mt][nt][2] + bv.x;
            o1.y = d[mt][nt][3] + bv.y;
            *(float2*)(g_G + (size_t)(r + 8) * GN + c) = o1;
        }
    }
}

// -------- grid barrier --------
__device__ __forceinline__ void grid_sync(unsigned& target) {
    __syncthreads();
    if (threadIdx.x == 0) {
        __threadfence();
        atomicAdd(&g_barcnt, 1u);
        volatile unsigned* p = &g_barcnt;
        while (*p < target) { __nanosleep(32); }
        __threadfence();
    }
    __syncthreads();
    target += gridDim.x;
}

// -------- persistent wavefront kernel --------
__global__ __launch_bounds__(256, 2) void persist_kernel(float* __restrict__ hmem) {
    __shared__ __nv_bfloat16 Ahi[128 * SP];
    __shared__ __nv_bfloat16 Alo[128 * SP];
    __shared__ __nv_bfloat16 Bhi[64 * SP];
    __shared__ __nv_bfloat16 Blo[64 * SP];
    __shared__ int c0s[128];
    __shared__ int c1s[128];
    int tid = threadIdx.x;
    int lane = tid & 31;
    int w = tid >> 5;
    int wm = w >> 1;
    int wn = w & 1;
    int g = lane >> 2;
    int tig = lane & 3;
    unsigned target = gridDim.x;

    int nlev = g_numlevels;
    for (int L = 0; L < nlev; L++) {
        int s0 = g_lvlstart[L];
        int nsteps = g_lvlstart[L + 1] - s0;

        // ---- phase A: recurrent GEMM tiles, 128 b-rows x 64 gate-cols, K=512 ----
        int ntasks = nsteps * 48;   // 4 btiles * 12 ntiles
        for (int task = blockIdx.x; task < ntasks; task += gridDim.x) {
            int t = g_order[s0 + task / 48];
            int tile = task % 48;
            int btile = (tile & 3) * 128;
            int ntile = (tile >> 2) * 64;

            if (tid < 128) {
                c0s[tid] = g_child0[t * BN + btile + tid];
                c1s[tid] = g_child1[t * BN + btile + tid];
            }
            __syncthreads();
            int act = __syncthreads_or((tid < 128) ? ((c0s[tid] >= 0) | (c1s[tid] >= 0)) : 0);
            if (!act) continue;

            float d[2][4][4];
            #pragma unroll
            for (int i = 0; i < 2; i++)
                #pragma unroll
                for (int j = 0; j < 4; j++)
                    #pragma unroll
                    for (int q = 0; q < 4; q++) d[i][j][q] = 0.f;

            for (int kb = 0; kb < K2; kb += 32) {
                int lower = (kb < MN) ? 1 : 0;
                int colb = kb & (MN - 1);
                #pragma unroll
                for (int j = 0; j < 2; j++) {
                    int id = tid + j * 256;
                    int row = id >> 2;
                    int g8 = id & 3;
                    int c = lower ? c0s[row] : c1s[row];
                    float4 va = make_float4(0.f, 0.f, 0.f, 0.f);
                    float4 vb = make_float4(0.f, 0.f, 0.f, 0.f);
                    if (c >= 0) {
                        const float* src = hmem + ((size_t)c * BN + btile + row) * MN + colb + g8 * 8;
                        va = *(const float4*)src;
                        vb = *(const float4*)(src + 4);
                    }
                    uint4 hi;
                    uint4 lo;
                    split8(va, vb, &hi, &lo);
                    *(uint4*)(Ahi + row * SP + g8 * 8) = hi;
                    *(uint4*)(Alo + row * SP + g8 * 8) = lo;
                }
                {
                    int id = tid;
                    int n = id >> 2;
                    int g8 = id & 3;
                    size_t idx = (size_t)(ntile + n) * K2 + kb + g8 * 8;
                    *(uint4*)(Bhi + n * SP + g8 * 8) = *(const uint4*)(g_W2hi + idx);
                    *(uint4*)(Blo + n * SP + g8 * 8) = *(const uint4*)(g_W2lo + idx);
                }
                __syncthreads();
                #pragma unroll
                for (int s = 0; s < 2; s++) {
                    int k0 = s * 16;
                    uint32_t ah[2][4];
                    uint32_t al[2][4];
                    uint32_t bh[4][2];
                    uint32_t bl[4][2];
                    #pragma unroll
                    for (int mt = 0; mt < 2; mt++) {
                        load_afrag(ah[mt], Ahi, wm * 32 + mt * 16, k0, g, tig);
                        load_afrag(al[mt], Alo, wm * 32 + mt * 16, k0, g, tig);
                    }
                    #pragma unroll
                    for (int nt = 0; nt < 4; nt++) {
                        load_bfrag(bh[nt], Bhi, wn * 32 + nt * 8, k0, g, tig);
                        load_bfrag(bl[nt], Blo, wn * 32 + nt * 8, k0, g, tig);
                    }
                    #pragma unroll
                    for (int mt = 0; mt < 2; mt++) {
                        #pragma unroll
                        for (int nt = 0; nt < 4; nt++) {
                            mma16816(d[mt][nt], ah[mt], bh[nt]);
                            mma16816(d[mt][nt], ah[mt], bl[nt]);
                            mma16816(d[mt][nt], al[mt], bh[nt]);
                        }
                    }
                }
                __syncthreads();
            }

            // accumulate into G
            #pragma unroll
            for (int mt = 0; mt < 2; mt++) {
                #pragma unroll
                for (int nt = 0; nt < 4; nt++) {
                    int r = btile + wm * 32 + mt * 16 + g;
                    int c = ntile + wn * 32 + nt * 8 + 2 * tig;
                    float* p0 = g_G + ((size_t)t * BN + r) * GN + c;
                    float2 v0 = *(float2*)p0;
                    v0.x += d[mt][nt][0];
                    v0.y += d[mt][nt][1];
                    *(float2*)p0 = v0;
                    float* p1 = g_G + ((size_t)t * BN + r + 8) * GN + c;
                    float2 v1 = *(float2*)p1;
                    v1.x += d[mt][nt][2];
                    v1.y += d[mt][nt][3];
                    *(float2*)p1 = v1;
                }
            }
        }
        grid_sync(target);

        // ---- phase B: epilogue ----
        int etasks = nsteps * 128;
        for (int task = blockIdx.x; task < etasks; task += gridDim.x) {
            int t = g_order[s0 + (task >> 7)];
            int sub = task & 127;
            int q = sub * 256 + tid;
            int b = q >> 6;
            int m0 = (q & 63) << 2;
            const float* Gp = g_G + ((size_t)t * BN + b) * GN;
            float4 gi = *(const float4*)(Gp + m0);
            float4 go = *(const float4*)(Gp + MN + m0);
            float4 gu = *(const float4*)(Gp + 2 * MN + m0);
            float vi[4];
            float vo[4];
            float vu[4];
            vi[0] = gi.x; vi[1] = gi.y; vi[2] = gi.z; vi[3] = gi.w;
            vo[0] = go.x; vo[1] = go.y; vo[2] = go.z; vo[3] = go.w;
            vu[0] = gu.x; vu[1] = gu.y; vu[2] = gu.z; vu[3] = gu.w;
            float h[4];
            #pragma unroll
            for (int j = 0; j < 4; j++) {
                float cc = sigf(vi[j]) * tanhf(vu[j]);
                h[j] = sigf(vo[j]) * tanhf(cc);
            }
            *(float4*)(hmem + ((size_t)t * BN + b) * MN + m0) = make_float4(h[0], h[1], h[2], h[3]);
        }
        grid_sync(target);
    }
}

// -------- root gather --------
__global__ void root_kernel(float* __restrict__ out, const float* __restrict__ hmem) {
    int b = blockIdx.x;
    int m = threadIdx.x;
    out[b * MN + m] = hmem[((size_t)g_root[b] * BN + b) * MN + m];
}

extern "C" void kernel_launch(void* const* d_in, const int* in_sizes, int n_in,
                              void* d_out, int out_size) {
    const float* X  = (const float*)d_in[0];
    const int*   ar = (const int*)  d_in[1];
    const float* Wi = (const float*)d_in[2];
    const float* bi = (const float*)d_in[3];
    const float* Wo = (const float*)d_in[4];
    const float* bo = (const float*)d_in[5];
    const float* Wu = (const float*)d_in[6];
    const float* bu = (const float*)d_in[7];
    const float* Ui = (const float*)d_in[10];
    const float* Uo = (const float*)d_in[11];
    const float* Uu = (const float*)d_in[12];

    float* out  = (float*)d_out;
    float* hmem = out + BN * MN;

    prep_kernel<<<128, 256>>>(Wi, bi, Wo, bo, Wu, bu, Ui, Uo, Uu);
    sched_kernel<<<1, BN>>>(ar);
    gemm_in_kernel<<<dim3((TN * BN) / 128, GN / 64), 256>>>(X);
    persist_kernel<<<GRID_P, 256>>>(hmem);
    root_kernel<<<BN, MN>>>(out, hmem);
}

// round 8
// speedup vs baseline: 4.3011x; 1.0155x over previous
#include <cuda_runtime.h>
#include <cuda_bf16.h>
#include <math.h>
#include <stdint.h>

#define TN  256
#define BN  512
#define INN 128
#define MN  256
#define GN  768
#define K2  512
#define GRID_P 296
#define SP  40   // padded smem row stride in bf16

// -------- device scratch --------
__device__ float g_G[(size_t)TN * BN * GN];
__device__ __nv_bfloat16 g_W1hi[GN * INN];
__device__ __nv_bfloat16 g_W1lo[GN * INN];
__device__ __nv_bfloat16 g_W2hi[GN * K2];
__device__ __nv_bfloat16 g_W2lo[GN * K2];
__device__ __nv_bfloat16 g_Xhi[(size_t)TN * BN * INN];
__device__ __nv_bfloat16 g_Xlo[(size_t)TN * BN * INN];
__device__ __nv_bfloat16 g_Hhi[(size_t)TN * BN * MN];
__device__ __nv_bfloat16 g_Hlo[(size_t)TN * BN * MN];
__device__ float g_bvec[GN];
__device__ int   g_child0[TN * BN];
__device__ int   g_child1[TN * BN];
__device__ int   g_root[BN];
__device__ int   g_order[TN];
__device__ int   g_lvlstart[TN + 2];
__device__ int   g_numlevels;
__device__ unsigned g_barcnt;

__device__ __forceinline__ float sigf(float x) { return 1.0f / (1.0f + expf(-x)); }

__device__ __forceinline__ uint32_t smem_u32(const void* p) {
    uint32_t a;
    asm("{ .reg .u64 t; cvta.to.shared.u64 t, %1; cvt.u32.u64 %0, t; }" : "=r"(a) : "l"(p));
    return a;
}

__device__ __forceinline__ void mma16816(float* d, const uint32_t* a, const uint32_t* b) {
    asm volatile(
        "mma.sync.aligned.m16n8k16.row.col.f32.bf16.bf16.f32 "
        "{%0,%1,%2,%3}, {%4,%5,%6,%7}, {%8,%9}, {%0,%1,%2,%3};"
        : "+f"(d[0]), "+f"(d[1]), "+f"(d[2]), "+f"(d[3])
        : "r"(a[0]), "r"(a[1]), "r"(a[2]), "r"(a[3]), "r"(b[0]), "r"(b[1]));
}

__device__ __forceinline__ void ldsm4(uint32_t* r, uint32_t addr) {
    asm volatile("ldmatrix.sync.aligned.m8n8.x4.shared.b16 {%0,%1,%2,%3}, [%4];"
                 : "=r"(r[0]), "=r"(r[1]), "=r"(r[2]), "=r"(r[3]) : "r"(addr));
}

__device__ __forceinline__ uint32_t packbf2(float x, float y) {
    __nv_bfloat162 v = __floats2bfloat162_rn(x, y);
    return *reinterpret_cast<uint32_t*>(&v);
}

// -------- prep: split weights + X into bf16 hi/lo --------
__global__ void prep_kernel(const float* __restrict__ X,
                            const float* __restrict__ Wi, const float* __restrict__ bi,
                            const float* __restrict__ Wo, const float* __restrict__ bo,
                            const float* __restrict__ Wu, const float* __restrict__ bu,
                            const float* __restrict__ Ui, const float* __restrict__ Uo,
                            const float* __restrict__ Uu) {
    int idx = blockIdx.x * blockDim.x + threadIdx.x;
    int stride = gridDim.x * blockDim.x;
    for (size_t i = idx; i < (size_t)TN * BN * INN; i += stride) {
        float x = X[i];
        __nv_bfloat16 h = __float2bfloat16_rn(x);
        g_Xhi[i] = h;
        g_Xlo[i] = __float2bfloat16_rn(x - __bfloat162float(h));
    }
    for (int i = idx; i < GN * INN; i += stride) {
        int n = i / INN;
        int k = i % INN;
        int g = n / MN;
        int m = n % MN;
        const float* W = (g == 0) ? Wi : ((g == 1) ? Wo : Wu);
        float x = W[m * INN + k];
        __nv_bfloat16 h = __float2bfloat16_rn(x);
        g_W1hi[i] = h;
        g_W1lo[i] = __float2bfloat16_rn(x - __bfloat162float(h));
    }
    for (int i = idx; i < GN * K2; i += stride) {
        int n = i / K2;
        int k = i % K2;
        int g = n / MN;
        int m = n % MN;
        const float* U = (g == 0) ? Ui : ((g == 1) ? Uo : Uu);
        int br = k / MN;
        int kk = k % MN;
        float x = U[br * MN * MN + m * MN + kk];
        __nv_bfloat16 h = __float2bfloat16_rn(x);
        g_W2hi[i] = h;
        g_W2lo[i] = __float2bfloat16_rn(x - __bfloat162float(h));
    }
    for (int i = idx; i < GN; i += stride) {
        int g = i / MN;
        int m = i % MN;
        const float* bb = (g == 0) ? bi : ((g == 1) ? bo : bu);
        g_bvec[i] = bb[m];
    }
}

// -------- scheduler --------
__global__ void sched_kernel(const int* __restrict__ arities) {
    __shared__ int s_lvl[TN];
    __shared__ int s_start[TN + 1];
    __shared__ int s_cur[TN + 1];
    __shared__ int s_max;
    int b = threadIdx.x;
    for (int i = b; i < TN; i += BN) s_lvl[i] = 0;
    for (int i = b; i < TN + 1; i += BN) s_cur[i] = 0;
    if (b == 0) { s_max = 0; g_barcnt = 0u; }
    __syncthreads();

    int stck[TN + 2];
    int lvl[TN];
    for (int i = 0; i < TN + 2; i++) stck[i] = 0;
    int sp = 1;
    for (int t = 0; t < TN; t++) {
        int a = arities[t * BN + b];
        int c0 = -1;
        int c1 = -1;
        if (a > 0) {
            int s = stck[max(sp, 0)];
            if (s < t) c0 = s;
        }
        if (a > 1) {
            int s = stck[max(sp - 1, 0)];
            if (s < t) c1 = s;
        }
        g_child0[t * BN + b] = c0;
        g_child1[t * BN + b] = c1;
        int L = 0;
        if (c0 >= 0) L = lvl[c0] + 1;
        if (c1 >= 0) L = max(L, lvl[c1] + 1);
        lvl[t] = L;
        atomicMax(&s_lvl[t], L);
        sp += 1 - abs(a);
        if (sp < 0) sp = 0;
        if (sp > TN + 1) sp = TN + 1;
        if (a != -1) stck[sp] = t;
    }
    g_root[b] = stck[max(sp, 0)];
    __syncthreads();

    if (b < TN) {
        atomicMax(&s_max, s_lvl[b]);
        atomicAdd(&s_cur[s_lvl[b]], 1);
    }
    __syncthreads();
    if (b == 0) {
        int nl = s_max + 1;
        int pos = 0;
        for (int L = 0; L < nl; L++) {
            s_start[L] = pos;
            g_lvlstart[L] = pos;
            pos += s_cur[L];
            s_cur[L] = 0;
        }
        g_lvlstart[nl] = pos;
        g_numlevels = nl;
    }
    __syncthreads();
    if (b < TN) {
        int L = s_lvl[b];
        int p = atomicAdd(&s_cur[L], 1);
        g_order[s_start[L] + p] = b;
    }
}

// -------- input GEMM (HMMA bf16 3-term, ldmatrix): G = X @ W1^T + bias --------
__global__ __launch_bounds__(256, 2) void gemm_in_kernel() {
    __shared__ __align__(16) __nv_bfloat16 Ahi[128 * SP];
    __shared__ __align__(16) __nv_bfloat16 Alo[128 * SP];
    __shared__ __align__(16) __nv_bfloat16 Bhi[64 * SP];
    __shared__ __align__(16) __nv_bfloat16 Blo[64 * SP];
    int tid = threadIdx.x;
    int lane = tid & 31;
    int w = tid >> 5;
    int wm = w >> 1;
    int wn = w & 1;
    int g = lane >> 2;
    int tig = lane & 3;
    int rtile = blockIdx.x * 128;
    int ntile = blockIdx.y * 64;

    uint32_t uAhi = smem_u32(Ahi);
    uint32_t uAlo = smem_u32(Alo);
    uint32_t uBhi = smem_u32(Bhi);
    uint32_t uBlo = smem_u32(Blo);
    int arow = lane & 15;
    int ak8 = (lane >> 4) << 3;
    int bnrow = (lane & 7) + ((lane >> 4) << 3);
    int bk8 = ((lane >> 3) & 1) << 3;

    float d[2][4][4];
    #pragma unroll
    for (int i = 0; i < 2; i++)
        #pragma unroll
        for (int j = 0; j < 4; j++)
            #pragma unroll
            for (int q = 0; q < 4; q++) d[i][j][q] = 0.f;

    for (int kb = 0; kb < INN; kb += 32) {
        #pragma unroll
        for (int j = 0; j < 2; j++) {
            int id = tid + j * 256;
            int row = id >> 2;
            int g8 = id & 3;
            size_t idx = (size_t)(rtile + row) * INN + kb + g8 * 8;
            *(uint4*)(Ahi + row * SP + g8 * 8) = *(const uint4*)(g_Xhi + idx);
            *(uint4*)(Alo + row * SP + g8 * 8) = *(const uint4*)(g_Xlo + idx);
        }
        {
            int n = tid >> 2;
            int g8 = tid & 3;
            size_t idx = (size_t)(ntile + n) * INN + kb + g8 * 8;
            *(uint4*)(Bhi + n * SP + g8 * 8) = *(const uint4*)(g_W1hi + idx);
            *(uint4*)(Blo + n * SP + g8 * 8) = *(const uint4*)(g_W1lo + idx);
        }
        __syncthreads();
        #pragma unroll
        for (int s = 0; s < 2; s++) {
            int k0 = s * 16;
            uint32_t ah[2][4];
            uint32_t al[2][4];
            uint32_t bh[2][4];
            uint32_t bl[2][4];
            #pragma unroll
            for (int mt = 0; mt < 2; mt++) {
                uint32_t off = (uint32_t)(((wm * 32 + mt * 16 + arow) * SP + k0 + ak8) * 2);
                ldsm4(ah[mt], uAhi + off);
                ldsm4(al[mt], uAlo + off);
            }
            #pragma unroll
            for (int p = 0; p < 2; p++) {
                uint32_t off = (uint32_t)(((wn * 32 + p * 16 + bnrow) * SP + k0 + bk8) * 2);
                ldsm4(bh[p], uBhi + off);
                ldsm4(bl[p], uBlo + off);
            }
            #pragma unroll
            for (int mt = 0; mt < 2; mt++) {
                #pragma unroll
                for (int p = 0; p < 2; p++) {
                    #pragma unroll
                    for (int q = 0; q < 2; q++) {
                        int nt = p * 2 + q;
                        mma16816(d[mt][nt], ah[mt], &bh[p][q * 2]);
                        mma16816(d[mt][nt], ah[mt], &bl[p][q * 2]);
                        mma16816(d[mt][nt], al[mt], &bh[p][q * 2]);
                    }
                }
            }
        }
        __syncthreads();
    }

    #pragma unroll
    for (int mt = 0; mt < 2; mt++) {
        #pragma unroll
        for (int nt = 0; nt < 4; nt++) {
            int r = rtile + wm * 32 + mt * 16 + g;
            int c = ntile + wn * 32 + nt * 8 + 2 * tig;
            float2 bv = *(const float2*)(g_bvec + c);
            float2 o0;
            o0.x = d[mt][nt][0] + bv.x;
            o0.y = d[mt][nt][1] + bv.y;
            *(float2*)(g_G + (size_t)r * GN + c) = o0;
            float2 o1;
            o1.x = d[mt][nt][2] + bv.x;
            o1.y = d[mt][nt][3] + bv.y;
            *(float2*)(g_G + (size_t)(r + 8) * GN + c) = o1;
        }
    }
}

// -------- grid barrier --------
__device__ __forceinline__ void grid_sync(unsigned& target) {
    __syncthreads();
    if (threadIdx.x == 0) {
        __threadfence();
        atomicAdd(&g_barcnt, 1u);
        volatile unsigned* p = &g_barcnt;
        while (*p < target) { __nanosleep(32); }
        __threadfence();
    }
    __syncthreads();
    target += gridDim.x;
}

// -------- persistent wavefront kernel --------
__global__ __launch_bounds__(256, 2) void persist_kernel(float* __restrict__ hmem) {
    __shared__ __align__(16) __nv_bfloat16 Ahi[128 * SP];
    __shared__ __align__(16) __nv_bfloat16 Alo[128 * SP];
    __shared__ __align__(16) __nv_bfloat16 Bhi[64 * SP];
    __shared__ __align__(16) __nv_bfloat16 Blo[64 * SP];
    __shared__ int c0s[128];
    __shared__ int c1s[128];
    int tid = threadIdx.x;
    int lane = tid & 31;
    int w = tid >> 5;
    int wm = w >> 1;
    int wn = w & 1;
    int g = lane >> 2;
    int tig = lane & 3;
    unsigned target = gridDim.x;

    uint32_t uAhi = smem_u32(Ahi);
    uint32_t uAlo = smem_u32(Alo);
    uint32_t uBhi = smem_u32(Bhi);
    uint32_t uBlo = smem_u32(Blo);
    int arow = lane & 15;
    int ak8 = (lane >> 4) << 3;
    int bnrow = (lane & 7) + ((lane >> 4) << 3);
    int bk8 = ((lane >> 3) & 1) << 3;

    int nlev = g_numlevels;
    for (int L = 0; L < nlev; L++) {
        int s0 = g_lvlstart[L];
        int nsteps = g_lvlstart[L + 1] - s0;

        // ---- phase A ----
        int ntasks = nsteps * 48;
        for (int task = blockIdx.x; task < ntasks; task += gridDim.x) {
            int t = g_order[s0 + task / 48];
            int tile = task % 48;
            int btile = (tile & 3) * 128;
            int ntile = (tile >> 2) * 64;

            if (tid < 128) {
                c0s[tid] = g_child0[t * BN + btile + tid];
                c1s[tid] = g_child1[t * BN + btile + tid];
            }
            __syncthreads();
            int act = __syncthreads_or((tid < 128) ? ((c0s[tid] >= 0) | (c1s[tid] >= 0)) : 0);
            if (!act) continue;

            float d[2][4][4];
            #pragma unroll
            for (int i = 0; i < 2; i++)
                #pragma unroll
                for (int j = 0; j < 4; j++)
                    #pragma unroll
                    for (int q = 0; q < 4; q++) d[i][j][q] = 0.f;

            for (int kb = 0; kb < K2; kb += 32) {
                int lower = (kb < MN) ? 1 : 0;
                int colb = kb & (MN - 1);
                #pragma unroll
                for (int j = 0; j < 2; j++) {
                    int id = tid + j * 256;
                    int row = id >> 2;
                    int g8 = id & 3;
                    int c = lower ? c0s[row] : c1s[row];
                    uint4 hi = make_uint4(0u, 0u, 0u, 0u);
                    uint4 lo = make_uint4(0u, 0u, 0u, 0u);
                    if (c >= 0) {
                        size_t idx = ((size_t)c * BN + btile + row) * MN + colb + g8 * 8;
                        hi = *(const uint4*)(g_Hhi + idx);
                        lo = *(const uint4*)(g_Hlo + idx);
                    }
                    *(uint4*)(Ahi + row * SP + g8 * 8) = hi;
                    *(uint4*)(Alo + row * SP + g8 * 8) = lo;
                }
                {
                    int n = tid >> 2;
                    int g8 = tid & 3;
                    size_t idx = (size_t)(ntile + n) * K2 + kb + g8 * 8;
                    *(uint4*)(Bhi + n * SP + g8 * 8) = *(const uint4*)(g_W2hi + idx);
                    *(uint4*)(Blo + n * SP + g8 * 8) = *(const uint4*)(g_W2lo + idx);
                }
                __syncthreads();
                #pragma unroll
                for (int s = 0; s < 2; s++) {
                    int k0 = s * 16;
                    uint32_t ah[2][4];
                    uint32_t al[2][4];
                    uint32_t bh[2][4];
                    uint32_t bl[2][4];
                    #pragma unroll
                    for (int mt = 0; mt < 2; mt++) {
                        uint32_t off = (uint32_t)(((wm * 32 + mt * 16 + arow) * SP + k0 + ak8) * 2);
                        ldsm4(ah[mt], uAhi + off);
                        ldsm4(al[mt], uAlo + off);
                    }
                    #pragma unroll
                    for (int p = 0; p < 2; p++) {
                        uint32_t off = (uint32_t)(((wn * 32 + p * 16 + bnrow) * SP + k0 + bk8) * 2);
                        ldsm4(bh[p], uBhi + off);
                        ldsm4(bl[p], uBlo + off);
                    }
                    #pragma unroll
                    for (int mt = 0; mt < 2; mt++) {
                        #pragma unroll
                        for (int p = 0; p < 2; p++) {
                            #pragma unroll
                            for (int q = 0; q < 2; q++) {
                                int nt = p * 2 + q;
                                mma16816(d[mt][nt], ah[mt], &bh[p][q * 2]);
                                mma16816(d[mt][nt], ah[mt], &bl[p][q * 2]);
                                mma16816(d[mt][nt], al[mt], &bh[p][q * 2]);
                            }
                        }
                    }
                }
                __syncthreads();
            }

            #pragma unroll
            for (int mt = 0; mt < 2; mt++) {
                #pragma unroll
                for (int nt = 0; nt < 4; nt++) {
                    int r = btile + wm * 32 + mt * 16 + g;
                    int c = ntile + wn * 32 + nt * 8 + 2 * tig;
                    float* p0 = g_G + ((size_t)t * BN + r) * GN + c;
                    float2 v0 = *(float2*)p0;
                    v0.x += d[mt][nt][0];
                    v0.y += d[mt][nt][1];
                    *(float2*)p0 = v0;
                    float* p1 = g_G + ((size_t)t * BN + r + 8) * GN + c;
                    float2 v1 = *(float2*)p1;
                    v1.x += d[mt][nt][2];
                    v1.y += d[mt][nt][3];
                    *(float2*)p1 = v1;
                }
            }
        }
        grid_sync(target);

        // ---- phase B ----
        int etasks = nsteps * 128;
        for (int task = blockIdx.x; task < etasks; task += gridDim.x) {
            int t = g_order[s0 + (task >> 7)];
            int sub = task & 127;
            int q = sub * 256 + tid;
            int b = q >> 6;
            int m0 = (q & 63) << 2;
            const float* Gp = g_G + ((size_t)t * BN + b) * GN;
            float4 gi = *(const float4*)(Gp + m0);
            float4 go = *(const float4*)(Gp + MN + m0);
            float4 gu = *(const float4*)(Gp + 2 * MN + m0);
            float vi[4];
            float vo[4];
            float vu[4];
            vi[0] = gi.x; vi[1] = gi.y; vi[2] = gi.z; vi[3] = gi.w;
            vo[0] = go.x; vo[1] = go.y; vo[2] = go.z; vo[3] = go.w;
            vu[0] = gu.x; vu[1] = gu.y; vu[2] = gu.z; vu[3] = gu.w;
            float h[4];
            float hh[4];
            float hl[4];
            #pragma unroll
            for (int j = 0; j < 4; j++) {
                float cc = sigf(vi[j]) * tanhf(vu[j]);
                h[j] = sigf(vo[j]) * tanhf(cc);
                __nv_bfloat16 hb = __float2bfloat16_rn(h[j]);
                hh[j] = __bfloat162float(hb);
                hl[j] = h[j] - hh[j];
            }
            size_t idx = ((size_t)t * BN + b) * MN + m0;
            *(float4*)(hmem + idx) = make_float4(h[0], h[1], h[2], h[3]);
            uint2 ph;
            ph.x = packbf2(hh[0], hh[1]);
            ph.y = packbf2(hh[2], hh[3]);
            *(uint2*)(g_Hhi + idx) = ph;
            uint2 pl;
            pl.x = packbf2(hl[0], hl[1]);
            pl.y = packbf2(hl[2], hl[3]);
            *(uint2*)(g_Hlo + idx) = pl;
        }
        grid_sync(target);
    }
}

// -------- root gather --------
__global__ void root_kernel(float* __restrict__ out, const float* __restrict__ hmem) {
    int b = blockIdx.x;
    int m = threadIdx.x;
    out[b * MN + m] = hmem[((size_t)g_root[b] * BN + b) * MN + m];
}

extern "C" void kernel_launch(void* const* d_in, const int* in_sizes, int n_in,
                              void* d_out, int out_size) {
    const float* X  = (const float*)d_in[0];
    const int*   ar = (const int*)  d_in[1];
    const float* Wi = (const float*)d_in[2];
    const float* bi = (const float*)d_in[3];
    const float* Wo = (const float*)d_in[4];
    const float* bo = (const float*)d_in[5];
    const float* Wu = (const float*)d_in[6];
    const float* bu = (const float*)d_in[7];
    const float* Ui = (const float*)d_in[10];
    const float* Uo = (const float*)d_in[11];
    const float* Uu = (const float*)d_in[12];

    float* out  = (float*)d_out;
    float* hmem = out + BN * MN;

    prep_kernel<<<512, 256>>>(X, Wi, bi, Wo, bo, Wu, bu, Ui, Uo, Uu);
    sched_kernel<<<1, BN>>>(ar);
    gemm_in_kernel<<<dim3((TN * BN) / 128, GN / 64), 256>>>();
    persist_kernel<<<GRID_P, 256>>>(hmem);
    root_kernel<<<BN, MN>>>(out, hmem);
}

// round 9
// speedup vs baseline: 6.1892x; 1.4390x over previous
#include <cuda_runtime.h>
#include <cuda_bf16.h>
#include <math.h>
#include <stdint.h>

#define TN  256
#define BN  512
#define INN 128
#define MN  256
#define KC  640          // fused K: 128 x + 2*256 children
#define NW  96           // N tile: 32 m * 3 gates
#define GRID_P 296
#define SP  40           // padded smem row stride (bf16)

// dynamic smem layout: 2 stages * 35840B; stage: Ahi 0, Alo 10240, Bhi 20480, Blo 28160
#define STG 35840
#define DSM (2 * STG)

// -------- device scratch --------
__device__ __nv_bfloat16 g_Wchi[768 * KC];   // fused weights [n'=3m+g][k]
__device__ __nv_bfloat16 g_Wclo[768 * KC];
__device__ __nv_bfloat16 g_Xhi[(size_t)TN * BN * INN];
__device__ __nv_bfloat16 g_Xlo[(size_t)TN * BN * INN];
__device__ __nv_bfloat16 g_Hhi[(size_t)TN * BN * MN];
__device__ __nv_bfloat16 g_Hlo[(size_t)TN * BN * MN];
__device__ float g_bc[768];                  // interleaved bias
__device__ int   g_child0[TN * BN];
__device__ int   g_child1[TN * BN];
__device__ int   g_root[BN];
__device__ int   g_order[TN];
__device__ int   g_lvlstart[TN + 2];
__device__ int   g_numlevels;
__device__ unsigned g_barcnt;

__device__ __forceinline__ float sigf(float x) { return 1.0f / (1.0f + expf(-x)); }

__device__ __forceinline__ uint32_t smem_u32(const void* p) {
    uint32_t a;
    asm("{ .reg .u64 t; cvta.to.shared.u64 t, %1; cvt.u32.u64 %0, t; }" : "=r"(a) : "l"(p));
    return a;
}

__device__ __forceinline__ void mma16816(float* d, const uint32_t* a, const uint32_t* b) {
    asm volatile(
        "mma.sync.aligned.m16n8k16.row.col.f32.bf16.bf16.f32 "
        "{%0,%1,%2,%3}, {%4,%5,%6,%7}, {%8,%9}, {%0,%1,%2,%3};"
        : "+f"(d[0]), "+f"(d[1]), "+f"(d[2]), "+f"(d[3])
        : "r"(a[0]), "r"(a[1]), "r"(a[2]), "r"(a[3]), "r"(b[0]), "r"(b[1]));
}

__device__ __forceinline__ void ldsm4(uint32_t* r, uint32_t addr) {
    asm volatile("ldmatrix.sync.aligned.m8n8.x4.shared.b16 {%0,%1,%2,%3}, [%4];"
                 : "=r"(r[0]), "=r"(r[1]), "=r"(r[2]), "=r"(r[3]) : "r"(addr));
}

__device__ __forceinline__ void cpa16(uint32_t dst, const void* src, int sz) {
    asm volatile("cp.async.ca.shared.global [%0], [%1], 16, %2;"
                 :: "r"(dst), "l"(src), "r"(sz) : "memory");
}
__device__ __forceinline__ void cpa_commit() {
    asm volatile("cp.async.commit_group;" ::: "memory");
}
__device__ __forceinline__ void cpa_wait1() {
    asm volatile("cp.async.wait_group 1;" ::: "memory");
}
__device__ __forceinline__ void cpa_wait0() {
    asm volatile("cp.async.wait_group 0;" ::: "memory");
}

__device__ __forceinline__ uint32_t packbf2(float x, float y) {
    __nv_bfloat162 v = __floats2bfloat162_rn(x, y);
    return *reinterpret_cast<uint32_t*>(&v);
}

// -------- prep: X split, fused interleaved weights, bias --------
__global__ void prep_kernel(const float* __restrict__ X,
                            const float* __restrict__ Wi, const float* __restrict__ bi,
                            const float* __restrict__ Wo, const float* __restrict__ bo,
                            const float* __restrict__ Wu, const float* __restrict__ bu,
                            const float* __restrict__ Ui, const float* __restrict__ Uo,
                            const float* __restrict__ Uu) {
    size_t idx = blockIdx.x * blockDim.x + threadIdx.x;
    size_t stride = (size_t)gridDim.x * blockDim.x;
    for (size_t i = idx; i < (size_t)TN * BN * INN; i += stride) {
        float x = X[i];
        __nv_bfloat16 h = __float2bfloat16_rn(x);
        g_Xhi[i] = h;
        g_Xlo[i] = __float2bfloat16_rn(x - __bfloat162float(h));
    }
    for (size_t i = idx; i < (size_t)768 * KC; i += stride) {
        int n = (int)(i / KC);
        int k = (int)(i % KC);
        int m = n / 3;
        int g = n % 3;
        float x;
        if (k < INN) {
            const float* W = (g == 0) ? Wi : ((g == 1) ? Wo : Wu);
            x = W[m * INN + k];
        } else {
            const float* U = (g == 0) ? Ui : ((g == 1) ? Uo : Uu);
            int br = (k - INN) / MN;
            int kk = (k - INN) % MN;
            x = U[br * MN * MN + m * MN + kk];
        }
        __nv_bfloat16 h = __float2bfloat16_rn(x);
        g_Wchi[i] = h;
        g_Wclo[i] = __float2bfloat16_rn(x - __bfloat162float(h));
    }
    for (size_t i = idx; i < 768; i += stride) {
        int m = (int)i / 3;
        int g = (int)i % 3;
        const float* bb = (g == 0) ? bi : ((g == 1) ? bo : bu);
        g_bc[i] = bb[m];
    }
}

// -------- scheduler --------
__global__ void sched_kernel(const int* __restrict__ arities) {
    __shared__ int s_lvl[TN];
    __shared__ int s_start[TN + 1];
    __shared__ int s_cur[TN + 1];
    __shared__ int s_max;
    int b = threadIdx.x;
    for (int i = b; i < TN; i += BN) s_lvl[i] = 0;
    for (int i = b; i < TN + 1; i += BN) s_cur[i] = 0;
    if (b == 0) { s_max = 0; g_barcnt = 0u; }
    __syncthreads();

    int stck[TN + 2];
    int lvl[TN];
    for (int i = 0; i < TN + 2; i++) stck[i] = 0;
    int sp = 1;
    for (int t = 0; t < TN; t++) {
        int a = arities[t * BN + b];
        int c0 = -1;
        int c1 = -1;
        if (a > 0) {
            int s = stck[max(sp, 0)];
            if (s < t) c0 = s;
        }
        if (a > 1) {
            int s = stck[max(sp - 1, 0)];
            if (s < t) c1 = s;
        }
        g_child0[t * BN + b] = c0;
        g_child1[t * BN + b] = c1;
        int L = 0;
        if (c0 >= 0) L = lvl[c0] + 1;
        if (c1 >= 0) L = max(L, lvl[c1] + 1);
        lvl[t] = L;
        atomicMax(&s_lvl[t], L);
        sp += 1 - abs(a);
        if (sp < 0) sp = 0;
        if (sp > TN + 1) sp = TN + 1;
        if (a != -1) stck[sp] = t;
    }
    g_root[b] = stck[max(sp, 0)];
    __syncthreads();

    if (b < TN) {
        atomicMax(&s_max, s_lvl[b]);
        atomicAdd(&s_cur[s_lvl[b]], 1);
    }
    __syncthreads();
    if (b == 0) {
        int nl = s_max + 1;
        int pos = 0;
        for (int L = 0; L < nl; L++) {
            s_start[L] = pos;
            g_lvlstart[L] = pos;
            pos += s_cur[L];
            s_cur[L] = 0;
        }
        g_lvlstart[nl] = pos;
        g_numlevels = nl;
    }
    __syncthreads();
    if (b < TN) {
        int L = s_lvl[b];
        int p = atomicAdd(&s_cur[L], 1);
        g_order[s_start[L] + p] = b;
    }
}

// -------- grid barrier --------
__device__ __forceinline__ void grid_sync(unsigned& target) {
    __syncthreads();
    if (threadIdx.x == 0) {
        __threadfence();
        atomicAdd(&g_barcnt, 1u);
        volatile unsigned* p = &g_barcnt;
        while (*p < target) { __nanosleep(32); }
        __threadfence();
    }
    __syncthreads();
    target += gridDim.x;
}

// -------- persistent fused kernel --------
// Task = (step t, btile 0..3, ntile 0..7): out tile 128 rows x 96 gate-cols (32 m x 3 gates),
// K = 640 fused [x | h_c0 | h_c1] (128 if no children). Fused LSTM epilogue writes h directly.
__global__ __launch_bounds__(256, 2) void persist_kernel(float* __restrict__ hmem) {
    extern __shared__ __align__(16) char dyn[];
    __shared__ int c0s[128];
    __shared__ int c1s[128];
    __shared__ float bcs[NW];
    int tid = threadIdx.x;
    int lane = tid & 31;
    int w = tid >> 5;
    int wm = w >> 1;
    int wn = w & 1;
    int g = lane >> 2;
    int tig = lane & 3;
    unsigned target = gridDim.x;

    uint32_t ubase = smem_u32(dyn);
    int arow = lane & 15;
    int ak8 = (lane >> 4) << 3;
    int bnrow = (lane & 7) + ((lane >> 4) << 3);
    int bk8 = ((lane >> 3) & 1) << 3;
    float* Xs = (float*)dyn;   // exchange buffer aliases pipeline stages

    int nlev = g_numlevels;
    for (int L = 0; L < nlev; L++) {
        int s0 = g_lvlstart[L];
        int ntasks = (g_lvlstart[L + 1] - s0) * 32;
        for (int task = blockIdx.x; task < ntasks; task += gridDim.x) {
            int t = g_order[s0 + (task >> 5)];
            int sub = task & 31;
            int btile = (sub & 3) * 128;
            int ntb = (sub >> 2) * NW;
            int m0 = (sub >> 2) * 32;

            __syncthreads();   // protect Xs / c0s from previous task
            if (tid < 128) {
                c0s[tid] = g_child0[t * BN + btile + tid];
                c1s[tid] = g_child1[t * BN + btile + tid];
            }
            if (tid < NW) bcs[tid] = g_bc[ntb + tid];
            __syncthreads();
            int act = __syncthreads_or((tid < 128) ? ((c0s[tid] >= 0) | (c1s[tid] >= 0)) : 0);
            int nch = act ? (KC / 32) : (INN / 32);

            float d[2][6][4];
            #pragma unroll
            for (int i = 0; i < 2; i++)
                #pragma unroll
                for (int j = 0; j < 6; j++)
                    #pragma unroll
                    for (int q = 0; q < 4; q++) d[i][j][q] = 0.f;

            // ---- fill chunk macro (as lambda) ----
            auto fill = [&](int ch) {
                int kc = ch * 32;
                uint32_t sb = ubase + (uint32_t)(ch & 1) * STG;
                // A: 128 rows x 32 cols, hi+lo
                #pragma unroll
                for (int j = 0; j < 2; j++) {
                    int id = tid + j * 256;
                    int row = id >> 2;
                    int seg = id & 3;
                    uint32_t doff = (uint32_t)(row * SP + seg * 8) * 2;
                    const __nv_bfloat16* sh;
                    const __nv_bfloat16* sl;
                    int sz = 16;
                    if (kc < INN) {
                        size_t o = ((size_t)t * BN + btile + row) * INN + kc + seg * 8;
                        sh = g_Xhi + o;
                        sl = g_Xlo + o;
                    } else {
                        int c = (kc < INN + MN) ? c0s[row] : c1s[row];
                        size_t o = 0;
                        if (c >= 0) {
                            int col = ((kc - INN) & (MN - 1)) + seg * 8;
                            o = ((size_t)c * BN + btile + row) * MN + col;
                        } else {
                            sz = 0;
                        }
                        sh = g_Hhi + o;
                        sl = g_Hlo + o;
                    }
                    cpa16(sb + doff, sh, sz);
                    cpa16(sb + 10240 + doff, sl, sz);
                }
                // B: 96 rows x 32 cols, hi+lo
                #pragma unroll
                for (int j = 0; j < 2; j++) {
                    int id = tid + j * 256;
                    if (id < 384) {
                        int row = id >> 2;
                        int seg = id & 3;
                        uint32_t doff = (uint32_t)(row * SP + seg * 8) * 2;
                        size_t o = (size_t)(ntb + row) * KC + kc + seg * 8;
                        cpa16(sb + 20480 + doff, g_Wchi + o, 16);
                        cpa16(sb + 28160 + doff, g_Wclo + o, 16);
                    }
                }
                cpa_commit();
            };

            fill(0);
            for (int ch = 0; ch < nch; ch++) {
                if (ch + 1 < nch) {
                    fill(ch + 1);
                    cpa_wait1();
                } else {
                    cpa_wait0();
                }
                __syncthreads();
                uint32_t sb = ubase + (uint32_t)(ch & 1) * STG;
                uint32_t uA = sb;
                uint32_t uAl = sb + 10240;
                uint32_t uB = sb + 20480;
                uint32_t uBl = sb + 28160;
                #pragma unroll
                for (int s16 = 0; s16 < 2; s16++) {
                    int k0 = s16 * 16;
                    uint32_t ah[2][4];
                    uint32_t al[2][4];
                    uint32_t bh[3][4];
                    uint32_t bl[3][4];
                    #pragma unroll
                    for (int mt = 0; mt < 2; mt++) {
                        uint32_t off = (uint32_t)(((wm * 32 + mt * 16 + arow) * SP + k0 + ak8) * 2);
                        ldsm4(ah[mt], uA + off);
                        ldsm4(al[mt], uAl + off);
                    }
                    #pragma unroll
                    for (int p = 0; p < 3; p++) {
                        uint32_t off = (uint32_t)(((wn * 48 + p * 16 + bnrow) * SP + k0 + bk8) * 2);
                        ldsm4(bh[p], uB + off);
                        ldsm4(bl[p], uBl + off);
                    }
                    #pragma unroll
                    for (int mt = 0; mt < 2; mt++) {
                        #pragma unroll
                        for (int p = 0; p < 3; p++) {
                            #pragma unroll
                            for (int q = 0; q < 2; q++) {
                                int nt = p * 2 + q;
                                mma16816(d[mt][nt], ah[mt], &bh[p][q * 2]);
                                mma16816(d[mt][nt], ah[mt], &bl[p][q * 2]);
                                mma16816(d[mt][nt], al[mt], &bh[p][q * 2]);
                            }
                        }
                    }
                }
                __syncthreads();
            }

            // ---- exchange: accum -> smem (stride 99) ----
            #pragma unroll
            for (int mt = 0; mt < 2; mt++) {
                #pragma unroll
                for (int nt = 0; nt < 6; nt++) {
                    int r0 = wm * 32 + mt * 16 + g;
                    int c0 = wn * 48 + nt * 8 + tig * 2;
                    Xs[r0 * 99 + c0] = d[mt][nt][0];
                    Xs[r0 * 99 + c0 + 1] = d[mt][nt][1];
                    Xs[(r0 + 8) * 99 + c0] = d[mt][nt][2];
                    Xs[(r0 + 8) * 99 + c0 + 1] = d[mt][nt][3];
                }
            }
            __syncthreads();

            // ---- fused LSTM epilogue: 2 threads per row, 16 m each ----
            {
                int row = tid >> 1;
                int mh = (tid & 1) * 16;
                float hv[16];
                #pragma unroll
                for (int mm = 0; mm < 16; mm++) {
                    int mj = mh + mm;
                    float vi = Xs[row * 99 + mj * 3 + 0] + bcs[mj * 3 + 0];
                    float vo = Xs[row * 99 + mj * 3 + 1] + bcs[mj * 3 + 1];
                    float vu = Xs[row * 99 + mj * 3 + 2] + bcs[mj * 3 + 2];
                    float cc = sigf(vi) * tanhf(vu);
                    hv[mm] = sigf(vo) * tanhf(cc);
                }
                size_t base = ((size_t)t * BN + btile + row) * MN + m0 + mh;
                #pragma unroll
                for (int q = 0; q < 4; q++) {
                    *(float4*)(hmem + base + q * 4) =
                        make_float4(hv[q * 4], hv[q * 4 + 1], hv[q * 4 + 2], hv[q * 4 + 3]);
                }
                uint32_t ph[8];
                uint32_t pl[8];
                #pragma unroll
                for (int q = 0; q < 8; q++) {
                    float h0 = hv[q * 2];
                    float h1 = hv[q * 2 + 1];
                    __nv_bfloat16 b0 = __float2bfloat16_rn(h0);
                    __nv_bfloat16 b1 = __float2bfloat16_rn(h1);
                    float f0 = __bfloat162float(b0);
                    float f1 = __bfloat162float(b1);
                    ph[q] = packbf2(f0, f1);
                    pl[q] = packbf2(h0 - f0, h1 - f1);
                }
                *(uint4*)(g_Hhi + base) = make_uint4(ph[0], ph[1], ph[2], ph[3]);
                *(uint4*)(g_Hhi + base + 8) = make_uint4(ph[4], ph[5], ph[6], ph[7]);
                *(uint4*)(g_Hlo + base) = make_uint4(pl[0], pl[1], pl[2], pl[3]);
                *(uint4*)(g_Hlo + base + 8) = make_uint4(pl[4], pl[5], pl[6], pl[7]);
            }
        }
        grid_sync(target);
    }
}

// -------- root gather --------
__global__ void root_kernel(float* __restrict__ out, const float* __restrict__ hmem) {
    int b = blockIdx.x;
    int m = threadIdx.x;
    out[b * MN + m] = hmem[((size_t)g_root[b] * BN + b) * MN + m];
}

extern "C" void kernel_launch(void* const* d_in, const int* in_sizes, int n_in,
                              void* d_out, int out_size) {
    const float* X  = (const float*)d_in[0];
    const int*   ar = (const int*)  d_in[1];
    const float* Wi = (const float*)d_in[2];
    const float* bi = (const float*)d_in[3];
    const float* Wo = (const float*)d_in[4];
    const float* bo = (const float*)d_in[5];
    const float* Wu = (const float*)d_in[6];
    const float* bu = (const float*)d_in[7];
    const float* Ui = (const float*)d_in[10];
    const float* Uo = (const float*)d_in[11];
    const float* Uu = (const float*)d_in[12];

    float* out  = (float*)d_out;
    float* hmem = out + BN * MN;

    cudaFuncSetAttribute(persist_kernel, cudaFuncAttributeMaxDynamicSharedMemorySize, DSM);

    prep_kernel<<<512, 256>>>(X, Wi, bi, Wo, bo, Wu, bu, Ui, Uo, Uu);
    sched_kernel<<<1, BN>>>(ar);
    persist_kernel<<<GRID_P, 256, DSM>>>(hmem);
    root_kernel<<<BN, MN>>>(out, hmem);
}